// round 1
// baseline (speedup 1.0000x reference)
#include <cuda_runtime.h>
#include <cstdint>

// out[c, i, j] = one_hot[i, c]      for c in [0,4)
// out[c, i, j] = one_hot[j, c-4]    for c in [4,8)
// one_hot: [L, 4] row-major float32, L = 4096
// out:     [8, L, L] float32
//
// Pure HBM-write-bound: 536.9 MB stores, <=64KB effective reads.
// Strategy: 128-bit streaming stores (__stcs), one float4 per thread.

#ifndef SEQEMB_BLOCK
#define SEQEMB_BLOCK 256
#endif

__global__ __launch_bounds__(SEQEMB_BLOCK)
void seq_embed_kernel(const float* __restrict__ oh, float4* __restrict__ out, int L)
{
    const int c  = blockIdx.z;                                   // 0..7 plane
    const int i  = blockIdx.y;                                   // row 0..L-1
    const int j4 = blockIdx.x * SEQEMB_BLOCK + threadIdx.x;      // float4 column index
    const int L4 = L >> 2;
    if (j4 >= L4) return;

    const size_t idx = ((size_t)c * L + (size_t)i) * (size_t)L4 + (size_t)j4;

    float4 v;
    if (c < 4) {
        // row-constant broadcast: one_hot[i, c]
        const float val = __ldg(&oh[i * 4 + c]);
        v = make_float4(val, val, val, val);
    } else {
        // column one-hot: out[c,i,j] = one_hot[j, c-4]; row content identical for all i,
        // so these 4 loads hit L1/L2 after the first touch of each line.
        const int cc = c - 4;
        const int j  = j4 << 2;
        v.x = __ldg(&oh[(j + 0) * 4 + cc]);
        v.y = __ldg(&oh[(j + 1) * 4 + cc]);
        v.z = __ldg(&oh[(j + 2) * 4 + cc]);
        v.w = __ldg(&oh[(j + 3) * 4 + cc]);
    }

    // Streaming store: 537MB output >> L2 (126MB), zero reuse -> evict-first hint.
    __stcs(&out[idx], v);
}

extern "C" void kernel_launch(void* const* d_in, const int* in_sizes, int n_in,
                              void* d_out, int out_size)
{
    const float* oh = (const float*)d_in[0];
    const int L = in_sizes[0] / 4;            // one_hot is [L, 4]
    const int L4 = L >> 2;

    dim3 block(SEQEMB_BLOCK);
    dim3 grid((L4 + SEQEMB_BLOCK - 1) / SEQEMB_BLOCK, L, 8);
    seq_embed_kernel<<<grid, block>>>(oh, (float4*)d_out, L);
}

// round 2
// speedup vs baseline: 2.1734x; 2.1734x over previous
#include <cuda_runtime.h>
#include <cstdint>

// out[c, i, j] = one_hot[i, c]      for c in [0,4)
// out[c, i, j] = one_hot[j, c-4]    for c in [4,8)
// one_hot: [L, 4] row-major float32, L = 4096
// out:     [8, L, L] float32  (536.9 MB of stores)
//
// R1 finding: L1=84.5% (bound), DRAM=35.9%. Cause: bottom-plane gather did
// 4 strided scalar LDGs/thread -> 64 L1 load wavefronts/warp vs 4 store
// wavefronts. Fix: transpose one_hot into a __device__ scratch [4][L] so the
// gather becomes one coalesced LDG.128 per thread (4 wavefronts/warp).

#ifndef SEQEMB_BLOCK
#define SEQEMB_BLOCK 256
#endif

#define MAX_L 4096
__device__ float g_oht[4][MAX_L];   // transposed one-hot, 64 KB scratch

__global__ void transpose_oh_kernel(const float* __restrict__ oh, int L)
{
    const int i = blockIdx.x * blockDim.x + threadIdx.x;
    if (i < L) {
        const float4 r = reinterpret_cast<const float4*>(oh)[i];  // row i of [L,4]
        g_oht[0][i] = r.x;
        g_oht[1][i] = r.y;
        g_oht[2][i] = r.z;
        g_oht[3][i] = r.w;
    }
}

__global__ __launch_bounds__(SEQEMB_BLOCK)
void seq_embed_kernel(const float* __restrict__ oh, float4* __restrict__ out, int L)
{
    const int c  = blockIdx.z;                                   // 0..7 plane
    const int i  = blockIdx.y;                                   // row 0..L-1
    const int j4 = blockIdx.x * SEQEMB_BLOCK + threadIdx.x;      // float4 column index
    const int L4 = L >> 2;
    if (j4 >= L4) return;

    const size_t idx = ((size_t)c * L + (size_t)i) * (size_t)L4 + (size_t)j4;

    float4 v;
    if (c < 4) {
        // row-constant broadcast: whole warp loads same address -> 1 wavefront
        const float val = __ldg(&oh[i * 4 + c]);
        v = make_float4(val, val, val, val);
    } else {
        // coalesced 16B/lane read of the transposed row; identical for all i,
        // so it stays L1-resident after first touch on each SM.
        v = *reinterpret_cast<const float4*>(&g_oht[c - 4][j4 << 2]);
    }

    // Streaming store: 537MB output >> L2 (126MB), zero reuse -> evict-first.
    __stcs(&out[idx], v);
}

extern "C" void kernel_launch(void* const* d_in, const int* in_sizes, int n_in,
                              void* d_out, int out_size)
{
    const float* oh = (const float*)d_in[0];
    const int L = in_sizes[0] / 4;            // one_hot is [L, 4]
    const int L4 = L >> 2;

    transpose_oh_kernel<<<(L + 255) / 256, 256>>>(oh, L);

    dim3 block(SEQEMB_BLOCK);
    dim3 grid((L4 + SEQEMB_BLOCK - 1) / SEQEMB_BLOCK, L, 8);
    seq_embed_kernel<<<grid, block>>>(oh, (float4*)d_out, L);
}